// round 1
// baseline (speedup 1.0000x reference)
#include <cuda_runtime.h>
#include <math.h>

// Problem dims
#define BB   8
#define HH   96
#define WW   96
#define CCH  512
#define DD   64
#define LL   192
#define NPOS (BB*HH*WW)   // 73728

// Scratch (device globals; no allocations allowed)
__device__ float g_q [(size_t)NPOS*DD];
__device__ float g_k [(size_t)NPOS*DD];
__device__ float g_v [(size_t)NPOS*CCH];
__device__ float g_S [(size_t)NPOS*LL];
__device__ float g_yv[(size_t)NPOS*CCH];

// ---------------------------------------------------------------------------
// K1: fp32 SGEMM  C[N,M] = A[N,K] @ B[K,M] + bias[M]
// BM=128, BN=64, BK=16, 256 threads (16x16), 8x4 microtile.
// Requires N%128==0, K%16==0, M%64==0 (true here).
// ---------------------------------------------------------------------------
__global__ __launch_bounds__(256) void sgemm_bias(
    const float* __restrict__ A, const float* __restrict__ Bm,
    const float* __restrict__ bias, float* __restrict__ Cc,
    int N, int K, int M)
{
    __shared__ float As[16][128];
    __shared__ float Bs[16][64];
    const int tid = threadIdx.x;
    const int tx = tid & 15, ty = tid >> 4;
    const int rowBase = blockIdx.y * 128;
    const int colBase = blockIdx.x * 64;

    float acc[8][4];
    #pragma unroll
    for (int i = 0; i < 8; i++)
        #pragma unroll
        for (int j = 0; j < 4; j++) acc[i][j] = 0.f;

    const int ar  = tid >> 2;          // 0..63
    const int akc = (tid & 3) * 4;     // 0,4,8,12
    const int bkr = tid >> 4;          // 0..15
    const int bc  = (tid & 15) * 4;    // 0..60

    for (int kt = 0; kt < K; kt += 16) {
        float4 a0 = *reinterpret_cast<const float4*>(&A[(size_t)(rowBase + ar     ) * K + kt + akc]);
        float4 a1 = *reinterpret_cast<const float4*>(&A[(size_t)(rowBase + ar + 64) * K + kt + akc]);
        As[akc+0][ar] = a0.x; As[akc+1][ar] = a0.y; As[akc+2][ar] = a0.z; As[akc+3][ar] = a0.w;
        As[akc+0][ar+64] = a1.x; As[akc+1][ar+64] = a1.y; As[akc+2][ar+64] = a1.z; As[akc+3][ar+64] = a1.w;
        *reinterpret_cast<float4*>(&Bs[bkr][bc]) =
            *reinterpret_cast<const float4*>(&Bm[(size_t)(kt + bkr) * M + colBase + bc]);
        __syncthreads();

        #pragma unroll
        for (int k = 0; k < 16; k++) {
            float ra[8];
            #pragma unroll
            for (int i = 0; i < 8; i++) ra[i] = As[k][ty*8 + i];
            float4 b4 = *reinterpret_cast<float4*>(&Bs[k][tx*4]);
            #pragma unroll
            for (int i = 0; i < 8; i++) {
                acc[i][0] = fmaf(ra[i], b4.x, acc[i][0]);
                acc[i][1] = fmaf(ra[i], b4.y, acc[i][1]);
                acc[i][2] = fmaf(ra[i], b4.z, acc[i][2]);
                acc[i][3] = fmaf(ra[i], b4.w, acc[i][3]);
            }
        }
        __syncthreads();
    }

    float4 bias4 = *reinterpret_cast<const float4*>(&bias[colBase + tx*4]);
    #pragma unroll
    for (int i = 0; i < 8; i++) {
        float4 o;
        o.x = acc[i][0] + bias4.x;
        o.y = acc[i][1] + bias4.y;
        o.z = acc[i][2] + bias4.z;
        o.w = acc[i][3] + bias4.w;
        *reinterpret_cast<float4*>(&Cc[(size_t)(rowBase + ty*8 + i) * M + colBase + tx*4]) = o;
    }
}

// ---------------------------------------------------------------------------
// K2: sv scores. One block per (b,w) column: S[b,h,w,g] = q[b,h,w,:]·k[b,g,w,:]
// with diagonal (g==h) masked to -1e30.
// smem: qcol[96][65] + kcol[96][65]  (padded to kill bank conflicts)
// ---------------------------------------------------------------------------
#define SMEM_SC (2*96*65*4)
__global__ __launch_bounds__(256) void sv_kernel() {
    extern __shared__ float sm[];
    float* qc = sm;
    float* kc = sm + 96*65;
    const int b = blockIdx.y, w = blockIdx.x;
    const int tid = threadIdx.x;
    for (int i = tid; i < 96*64; i += 256) {
        int h = i >> 6, d = i & 63;
        size_t gi = ((size_t)((b*HH + h)*WW) + w)*DD + d;
        qc[h*65 + d] = g_q[gi];
        kc[h*65 + d] = g_k[gi];
    }
    __syncthreads();
    const int tx = tid & 15, ty = tid >> 4;
    const int h0 = ty*6, g0 = tx*6;
    float acc[6][6];
    #pragma unroll
    for (int i = 0; i < 6; i++)
        #pragma unroll
        for (int j = 0; j < 6; j++) acc[i][j] = 0.f;
    for (int d = 0; d < 64; d++) {
        float qa[6], ka[6];
        #pragma unroll
        for (int i = 0; i < 6; i++) qa[i] = qc[(h0+i)*65 + d];
        #pragma unroll
        for (int j = 0; j < 6; j++) ka[j] = kc[(g0+j)*65 + d];
        #pragma unroll
        for (int i = 0; i < 6; i++)
            #pragma unroll
            for (int j = 0; j < 6; j++) acc[i][j] = fmaf(qa[i], ka[j], acc[i][j]);
    }
    #pragma unroll
    for (int i = 0; i < 6; i++) {
        int h = h0 + i;
        size_t base = ((size_t)((b*HH + h)*WW) + w)*LL;
        #pragma unroll
        for (int j = 0; j < 6; j++) {
            int g = g0 + j;
            g_S[base + g] = (g == h) ? -1e30f : acc[i][j];
        }
    }
}

// ---------------------------------------------------------------------------
// K3: sh scores. One block per (b,h) row: S[b,h,w,96+u] = q[b,h,w,:]·k[b,h,u,:]
// ---------------------------------------------------------------------------
__global__ __launch_bounds__(256) void sh_kernel() {
    extern __shared__ float sm[];
    float* qr = sm;
    float* kr = sm + 96*65;
    const int b = blockIdx.y, h = blockIdx.x;
    const int tid = threadIdx.x;
    const size_t base = (size_t)(b*HH + h)*WW*DD;  // contiguous 96*64 slice
    for (int i = tid; i < 96*64; i += 256) {
        int wq = i >> 6, d = i & 63;
        qr[wq*65 + d] = g_q[base + i];
        kr[wq*65 + d] = g_k[base + i];
    }
    __syncthreads();
    const int tx = tid & 15, ty = tid >> 4;
    const int w0 = ty*6, u0 = tx*6;
    float acc[6][6];
    #pragma unroll
    for (int i = 0; i < 6; i++)
        #pragma unroll
        for (int j = 0; j < 6; j++) acc[i][j] = 0.f;
    for (int d = 0; d < 64; d++) {
        float qa[6], ka[6];
        #pragma unroll
        for (int i = 0; i < 6; i++) qa[i] = qr[(w0+i)*65 + d];
        #pragma unroll
        for (int j = 0; j < 6; j++) ka[j] = kr[(u0+j)*65 + d];
        #pragma unroll
        for (int i = 0; i < 6; i++)
            #pragma unroll
            for (int j = 0; j < 6; j++) acc[i][j] = fmaf(qa[i], ka[j], acc[i][j]);
    }
    #pragma unroll
    for (int i = 0; i < 6; i++) {
        size_t sbase = ((size_t)((b*HH + h)*WW) + (w0+i))*LL + 96;
        #pragma unroll
        for (int j = 0; j < 6; j++) g_S[sbase + u0 + j] = acc[i][j];
    }
}

// ---------------------------------------------------------------------------
// K4: softmax over the 192-long concatenated score row, in place.
// One warp per position; 4 warps per block.
// ---------------------------------------------------------------------------
__global__ __launch_bounds__(128) void softmax_kernel() {
    const int lane = threadIdx.x & 31;
    const size_t pos = (size_t)blockIdx.x * 4 + (threadIdx.x >> 5);
    float* s = g_S + pos * LL;
    float v[6];
    float m = -3.4e38f;
    #pragma unroll
    for (int i = 0; i < 6; i++) { v[i] = s[lane + 32*i]; m = fmaxf(m, v[i]); }
    #pragma unroll
    for (int o = 16; o; o >>= 1) m = fmaxf(m, __shfl_xor_sync(0xffffffffu, m, o));
    float sum = 0.f;
    #pragma unroll
    for (int i = 0; i < 6; i++) { v[i] = expf(v[i] - m); sum += v[i]; }
    #pragma unroll
    for (int o = 16; o; o >>= 1) sum += __shfl_xor_sync(0xffffffffu, sum, o);
    const float inv = 1.f / sum;
    #pragma unroll
    for (int i = 0; i < 6; i++) s[lane + 32*i] = v[i] * inv;
}

// ---------------------------------------------------------------------------
// K5: yv. One block per (b,w): yv[h,:] = sum_g av[h,g] * v[b,g,w,:]
// smem: Av[96][97] + Vc chunk[96][128]
// ---------------------------------------------------------------------------
#define SMEM_Y ((96*97 + 96*128)*4)
__global__ __launch_bounds__(256) void yv_kernel() {
    extern __shared__ float sm[];
    float* Av = sm;              // 96*97
    float* Vc = sm + 96*97;      // 96*128
    const int b = blockIdx.y, w = blockIdx.x;
    const int tid = threadIdx.x;
    for (int i = tid; i < 96*96; i += 256) {
        int h = i / 96, g = i - h*96;
        Av[h*97 + g] = g_S[((size_t)((b*HH + h)*WW) + w)*LL + g];
    }
    const int tx = tid & 15, ty = tid >> 4;
    const int h0 = ty*6, ct = tx*8;
    for (int c0 = 0; c0 < CCH; c0 += 128) {
        __syncthreads();   // Av ready (first iter) / previous compute done
        for (int i = tid*4; i < 96*128; i += 1024) {
            int g = i >> 7, cc = i & 127;
            *reinterpret_cast<float4*>(&Vc[g*128 + cc]) =
                *reinterpret_cast<const float4*>(&g_v[((size_t)((b*HH + g)*WW) + w)*CCH + c0 + cc]);
        }
        __syncthreads();
        float acc[6][8];
        #pragma unroll
        for (int i = 0; i < 6; i++)
            #pragma unroll
            for (int j = 0; j < 8; j++) acc[i][j] = 0.f;
        for (int g = 0; g < 96; g++) {
            float a[6];
            #pragma unroll
            for (int i = 0; i < 6; i++) a[i] = Av[(h0+i)*97 + g];
            float4 v0 = *reinterpret_cast<float4*>(&Vc[g*128 + ct]);
            float4 v1 = *reinterpret_cast<float4*>(&Vc[g*128 + ct + 4]);
            #pragma unroll
            for (int i = 0; i < 6; i++) {
                acc[i][0] = fmaf(a[i], v0.x, acc[i][0]);
                acc[i][1] = fmaf(a[i], v0.y, acc[i][1]);
                acc[i][2] = fmaf(a[i], v0.z, acc[i][2]);
                acc[i][3] = fmaf(a[i], v0.w, acc[i][3]);
                acc[i][4] = fmaf(a[i], v1.x, acc[i][4]);
                acc[i][5] = fmaf(a[i], v1.y, acc[i][5]);
                acc[i][6] = fmaf(a[i], v1.z, acc[i][6]);
                acc[i][7] = fmaf(a[i], v1.w, acc[i][7]);
            }
        }
        #pragma unroll
        for (int i = 0; i < 6; i++) {
            size_t o = ((size_t)((b*HH + h0 + i)*WW) + w)*CCH + c0 + ct;
            *reinterpret_cast<float4*>(&g_yv[o]) =
                make_float4(acc[i][0], acc[i][1], acc[i][2], acc[i][3]);
            *reinterpret_cast<float4*>(&g_yv[o+4]) =
                make_float4(acc[i][4], acc[i][5], acc[i][6], acc[i][7]);
        }
    }
}

// ---------------------------------------------------------------------------
// K6: yh + epilogue. One block per (b,h):
//   out[w,:] = (yh[w,:] + yv[w,:]) * gamma + x[w,:]
// ---------------------------------------------------------------------------
__global__ __launch_bounds__(256) void yh_final_kernel(
    const float* __restrict__ x, const float* __restrict__ gamma,
    float* __restrict__ out)
{
    extern __shared__ float sm[];
    float* Ah = sm;              // 96*97
    float* Vr = sm + 96*97;      // 96*128
    const int b = blockIdx.y, h = blockIdx.x;
    const int tid = threadIdx.x;
    for (int i = tid; i < 96*96; i += 256) {
        int wq = i / 96, u = i - wq*96;
        Ah[wq*97 + u] = g_S[((size_t)((b*HH + h)*WW) + wq)*LL + 96 + u];
    }
    const float gm = *gamma;
    const int tx = tid & 15, ty = tid >> 4;
    const int w0 = ty*6, ct = tx*8;
    const size_t rowbase = (size_t)(b*HH + h)*WW;
    for (int c0 = 0; c0 < CCH; c0 += 128) {
        __syncthreads();
        for (int i = tid*4; i < 96*128; i += 1024) {
            int u = i >> 7, cc = i & 127;
            *reinterpret_cast<float4*>(&Vr[u*128 + cc]) =
                *reinterpret_cast<const float4*>(&g_v[(rowbase + u)*CCH + c0 + cc]);
        }
        __syncthreads();
        float acc[6][8];
        #pragma unroll
        for (int i = 0; i < 6; i++)
            #pragma unroll
            for (int j = 0; j < 8; j++) acc[i][j] = 0.f;
        for (int u = 0; u < 96; u++) {
            float a[6];
            #pragma unroll
            for (int i = 0; i < 6; i++) a[i] = Ah[(w0+i)*97 + u];
            float4 v0 = *reinterpret_cast<float4*>(&Vr[u*128 + ct]);
            float4 v1 = *reinterpret_cast<float4*>(&Vr[u*128 + ct + 4]);
            #pragma unroll
            for (int i = 0; i < 6; i++) {
                acc[i][0] = fmaf(a[i], v0.x, acc[i][0]);
                acc[i][1] = fmaf(a[i], v0.y, acc[i][1]);
                acc[i][2] = fmaf(a[i], v0.z, acc[i][2]);
                acc[i][3] = fmaf(a[i], v0.w, acc[i][3]);
                acc[i][4] = fmaf(a[i], v1.x, acc[i][4]);
                acc[i][5] = fmaf(a[i], v1.y, acc[i][5]);
                acc[i][6] = fmaf(a[i], v1.z, acc[i][6]);
                acc[i][7] = fmaf(a[i], v1.w, acc[i][7]);
            }
        }
        #pragma unroll
        for (int i = 0; i < 6; i++) {
            size_t o = (rowbase + w0 + i)*CCH + c0 + ct;
            float4 yv0 = *reinterpret_cast<const float4*>(&g_yv[o]);
            float4 yv1 = *reinterpret_cast<const float4*>(&g_yv[o+4]);
            float4 x0  = *reinterpret_cast<const float4*>(&x[o]);
            float4 x1  = *reinterpret_cast<const float4*>(&x[o+4]);
            float4 r0, r1;
            r0.x = fmaf(acc[i][0] + yv0.x, gm, x0.x);
            r0.y = fmaf(acc[i][1] + yv0.y, gm, x0.y);
            r0.z = fmaf(acc[i][2] + yv0.z, gm, x0.z);
            r0.w = fmaf(acc[i][3] + yv0.w, gm, x0.w);
            r1.x = fmaf(acc[i][4] + yv1.x, gm, x1.x);
            r1.y = fmaf(acc[i][5] + yv1.y, gm, x1.y);
            r1.z = fmaf(acc[i][6] + yv1.z, gm, x1.z);
            r1.w = fmaf(acc[i][7] + yv1.w, gm, x1.w);
            *reinterpret_cast<float4*>(&out[o])   = r0;
            *reinterpret_cast<float4*>(&out[o+4]) = r1;
        }
    }
}

// ---------------------------------------------------------------------------
extern "C" void kernel_launch(void* const* d_in, const int* in_sizes, int n_in,
                              void* d_out, int out_size)
{
    const float* x     = (const float*)d_in[0];
    const float* Wq    = (const float*)d_in[1];
    const float* bq    = (const float*)d_in[2];
    const float* Wk    = (const float*)d_in[3];
    const float* bk    = (const float*)d_in[4];
    const float* Wv    = (const float*)d_in[5];
    const float* bv    = (const float*)d_in[6];
    const float* gamma = (const float*)d_in[7];
    float* out = (float*)d_out;

    float *qp, *kp, *vp;
    cudaGetSymbolAddress((void**)&qp, g_q);
    cudaGetSymbolAddress((void**)&kp, g_k);
    cudaGetSymbolAddress((void**)&vp, g_v);

    cudaFuncSetAttribute(sv_kernel,       cudaFuncAttributeMaxDynamicSharedMemorySize, SMEM_SC);
    cudaFuncSetAttribute(sh_kernel,       cudaFuncAttributeMaxDynamicSharedMemorySize, SMEM_SC);
    cudaFuncSetAttribute(yv_kernel,       cudaFuncAttributeMaxDynamicSharedMemorySize, SMEM_Y);
    cudaFuncSetAttribute(yh_final_kernel, cudaFuncAttributeMaxDynamicSharedMemorySize, SMEM_Y);

    // Projections: q, k (M=64), v (M=512)
    sgemm_bias<<<dim3(DD/64,  NPOS/128), 256>>>(x, Wq, bq, qp, NPOS, CCH, DD);
    sgemm_bias<<<dim3(DD/64,  NPOS/128), 256>>>(x, Wk, bk, kp, NPOS, CCH, DD);
    sgemm_bias<<<dim3(CCH/64, NPOS/128), 256>>>(x, Wv, bv, vp, NPOS, CCH, CCH);

    // Scores (column + row), masked diag in sv
    sv_kernel<<<dim3(WW, BB), 256, SMEM_SC>>>();
    sh_kernel<<<dim3(HH, BB), 256, SMEM_SC>>>();

    // Joint softmax over 192, in place
    softmax_kernel<<<NPOS/4, 128>>>();

    // Attention application + epilogue
    yv_kernel<<<dim3(WW, BB), 256, SMEM_Y>>>();
    yh_final_kernel<<<dim3(HH, BB), 256, SMEM_Y>>>(x, gamma, out);
}

// round 4
// speedup vs baseline: 1.7888x; 1.7888x over previous
#include <cuda_runtime.h>
#include <math.h>
#include <stdint.h>

// Problem dims
#define BB   8
#define HH   96
#define WW   96
#define CCH  512
#define DD   64
#define LL   192
#define NPOS (BB*HH*WW)   // 73728

// ---------------------------------------------------------------------------
// Scratch (device globals; no allocations allowed)
// ---------------------------------------------------------------------------
__device__ float g_q [(size_t)NPOS*DD];
__device__ float g_k [(size_t)NPOS*DD];
__device__ float g_v [(size_t)NPOS*CCH];
__device__ float g_S [(size_t)NPOS*LL];
__device__ float g_yv[(size_t)NPOS*CCH];

// ---------------------------------------------------------------------------
// Helpers: tf32 convert, mma.sync, cp.async (all baseline PTX, sm_80+)
// ---------------------------------------------------------------------------
__device__ __forceinline__ uint32_t smem_u32(const void* p) {
    uint32_t a;
    asm("{ .reg .u64 t; cvta.to.shared.u64 t, %1; cvt.u32.u64 %0, t; }" : "=r"(a) : "l"(p));
    return a;
}
__device__ __forceinline__ uint32_t f2tf32(float f) {
    uint32_t r;
    asm("cvt.rna.tf32.f32 %0, %1;" : "=r"(r) : "f"(f));
    return r;
}
__device__ __forceinline__ void mma_tf32(
    float& c0, float& c1, float& c2, float& c3,
    uint32_t a0, uint32_t a1, uint32_t a2, uint32_t a3,
    uint32_t b0, uint32_t b1)
{
    asm volatile(
        "mma.sync.aligned.m16n8k8.row.col.f32.tf32.tf32.f32 "
        "{%0,%1,%2,%3}, {%4,%5,%6,%7}, {%8,%9}, {%0,%1,%2,%3};"
        : "+f"(c0), "+f"(c1), "+f"(c2), "+f"(c3)
        : "r"(a0), "r"(a1), "r"(a2), "r"(a3), "r"(b0), "r"(b1));
}
__device__ __forceinline__ void cpasync16(uint32_t dst, const void* src) {
    asm volatile("cp.async.cg.shared.global [%0], [%1], 16;" :: "r"(dst), "l"(src));
}
#define CP_COMMIT() asm volatile("cp.async.commit_group;" ::: "memory")
#define CP_WAIT(n)  asm volatile("cp.async.wait_group %0;" :: "n"(n) : "memory")

// ---------------------------------------------------------------------------
// K1: tf32 tensor-core projection GEMM
//   C[r, n0+c] = sum_k X[r,k] * W[k, n0+c] + bias[c]
//   BM=128, BK=32, BN template (128 for v, 64 for q/k). 256 threads = 8 warps
//   in 2(m) x 4(n); warp tile 64 x BN/4; m16n8k8 tf32, fp32 accum.
//   Double-buffered cp.async. A smem [m][36] (fp32), B smem [k][BN+8].
// ---------------------------------------------------------------------------
template<int BN>
__global__ __launch_bounds__(256) void proj_mma(
    const float* __restrict__ X, const float* __restrict__ W,
    const float* __restrict__ bias, float* __restrict__ C, int M)
{
    constexpr int BM = 128, BK = 32;
    constexpr int AP = 36, BP = BN + 8;
    constexpr int ASZ = BM * AP;          // floats
    constexpr int BSZ = BK * BP;
    constexpr int NCH = CCH / BK;         // 16
    constexpr int WN  = BN / 4;           // warp n-width: 32 or 16
    constexpr int NT  = WN / 8;           // n-tiles per warp: 4 or 2

    extern __shared__ float sm[];
    const uint32_t sbase = smem_u32(sm);
    const int tid = threadIdx.x;
    const int wid = tid >> 5, lane = tid & 31;
    const int gid = lane >> 2, tg = lane & 3;
    const int wm = wid >> 2, wn = wid & 3;
    const int rowBase = blockIdx.y * BM;
    const int n0 = blockIdx.x * BN;

    float acc[4][NT][4];
    #pragma unroll
    for (int mt = 0; mt < 4; mt++)
        #pragma unroll
        for (int nt = 0; nt < NT; nt++)
            #pragma unroll
            for (int i = 0; i < 4; i++) acc[mt][nt][i] = 0.f;

    // async-copy one K-chunk into buffer `buf`
    auto issue = [&](int ch, int buf) {
        const int kc = ch * BK;
        const uint32_t abase = sbase + (uint32_t)(buf * (ASZ + BSZ)) * 4u;
        const uint32_t bbase = abase + (uint32_t)ASZ * 4u;
        #pragma unroll
        for (int i = 0; i < 4; i++) {               // A: 1024 float4
            int idx = tid + i * 256;
            int r = idx >> 3, c4 = idx & 7;
            cpasync16(abase + (uint32_t)(r * AP + c4 * 4) * 4u,
                      &X[(size_t)(rowBase + r) * CCH + kc + c4 * 4]);
        }
        #pragma unroll
        for (int i = 0; i < BK * BN / 4 / 256; i++) { // B: BK*BN/4 float4
            int idx = tid + i * 256;
            int kr = idx / (BN / 4), c4 = idx % (BN / 4);
            cpasync16(bbase + (uint32_t)(kr * BP + c4 * 4) * 4u,
                      &W[(size_t)(kc + kr) * M + n0 + c4 * 4]);
        }
        CP_COMMIT();
    };

    issue(0, 0);
    for (int ch = 0; ch < NCH; ch++) {
        const int buf = ch & 1;
        if (ch + 1 < NCH) { issue(ch + 1, buf ^ 1); CP_WAIT(1); }
        else              { CP_WAIT(0); }
        __syncthreads();

        const float* Ab = sm + buf * (ASZ + BSZ);
        const float* Bb = Ab + ASZ;
        #pragma unroll
        for (int ks = 0; ks < 4; ks++) {
            const int k0 = ks * 8;
            uint32_t a[4][4];
            #pragma unroll
            for (int mt = 0; mt < 4; mt++) {
                const int m = wm * 64 + mt * 16;
                a[mt][0] = f2tf32(Ab[(m + gid)     * AP + k0 + tg]);
                a[mt][1] = f2tf32(Ab[(m + 8 + gid) * AP + k0 + tg]);
                a[mt][2] = f2tf32(Ab[(m + gid)     * AP + k0 + tg + 4]);
                a[mt][3] = f2tf32(Ab[(m + 8 + gid) * AP + k0 + tg + 4]);
            }
            uint32_t b[NT][2];
            #pragma unroll
            for (int nt = 0; nt < NT; nt++) {
                const int col = wn * WN + nt * 8 + gid;
                b[nt][0] = f2tf32(Bb[(k0 + tg)     * BP + col]);
                b[nt][1] = f2tf32(Bb[(k0 + tg + 4) * BP + col]);
            }
            #pragma unroll
            for (int mt = 0; mt < 4; mt++)
                #pragma unroll
                for (int nt = 0; nt < NT; nt++)
                    mma_tf32(acc[mt][nt][0], acc[mt][nt][1], acc[mt][nt][2], acc[mt][nt][3],
                             a[mt][0], a[mt][1], a[mt][2], a[mt][3],
                             b[nt][0], b[nt][1]);
        }
        __syncthreads();
    }

    // Epilogue: c0=C[row][col], c1=C[row][col+1], c2=C[row+8][col], c3=C[row+8][col+1]
    #pragma unroll
    for (int mt = 0; mt < 4; mt++) {
        const int row = rowBase + wm * 64 + mt * 16 + gid;
        #pragma unroll
        for (int nt = 0; nt < NT; nt++) {
            const int col = n0 + wn * WN + nt * 8 + tg * 2;
            const float b0 = bias[col], b1 = bias[col + 1];
            C[(size_t)row * M + col]           = acc[mt][nt][0] + b0;
            C[(size_t)row * M + col + 1]       = acc[mt][nt][1] + b1;
            C[(size_t)(row + 8) * M + col]     = acc[mt][nt][2] + b0;
            C[(size_t)(row + 8) * M + col + 1] = acc[mt][nt][3] + b1;
        }
    }
}

#define P_SMEM_V ((128*36 + 32*(128+8)) * 2 * 4)
#define P_SMEM_QK ((128*36 + 32*(64+8)) * 2 * 4)

// ---------------------------------------------------------------------------
// K2: sv scores. One block per (b,w) column; diag masked.
// ---------------------------------------------------------------------------
#define SMEM_SC (2*96*65*4)
__global__ __launch_bounds__(256) void sv_kernel() {
    extern __shared__ float sm[];
    float* qc = sm;
    float* kc = sm + 96*65;
    const int b = blockIdx.y, w = blockIdx.x;
    const int tid = threadIdx.x;
    for (int i = tid; i < 96*64; i += 256) {
        int h = i >> 6, d = i & 63;
        size_t gi = ((size_t)((b*HH + h)*WW) + w)*DD + d;
        qc[h*65 + d] = g_q[gi];
        kc[h*65 + d] = g_k[gi];
    }
    __syncthreads();
    const int tx = tid & 15, ty = tid >> 4;
    const int h0 = ty*6, g0 = tx*6;
    float acc[6][6];
    #pragma unroll
    for (int i = 0; i < 6; i++)
        #pragma unroll
        for (int j = 0; j < 6; j++) acc[i][j] = 0.f;
    for (int d = 0; d < 64; d++) {
        float qa[6], ka[6];
        #pragma unroll
        for (int i = 0; i < 6; i++) qa[i] = qc[(h0+i)*65 + d];
        #pragma unroll
        for (int j = 0; j < 6; j++) ka[j] = kc[(g0+j)*65 + d];
        #pragma unroll
        for (int i = 0; i < 6; i++)
            #pragma unroll
            for (int j = 0; j < 6; j++) acc[i][j] = fmaf(qa[i], ka[j], acc[i][j]);
    }
    #pragma unroll
    for (int i = 0; i < 6; i++) {
        int h = h0 + i;
        size_t base = ((size_t)((b*HH + h)*WW) + w)*LL;
        #pragma unroll
        for (int j = 0; j < 6; j++) {
            int g = g0 + j;
            g_S[base + g] = (g == h) ? -1e30f : acc[i][j];
        }
    }
}

// ---------------------------------------------------------------------------
// K3: sh scores. One block per (b,h) row.
// ---------------------------------------------------------------------------
__global__ __launch_bounds__(256) void sh_kernel() {
    extern __shared__ float sm[];
    float* qr = sm;
    float* kr = sm + 96*65;
    const int b = blockIdx.y, h = blockIdx.x;
    const int tid = threadIdx.x;
    const size_t base = (size_t)(b*HH + h)*WW*DD;
    for (int i = tid; i < 96*64; i += 256) {
        int wq = i >> 6, d = i & 63;
        qr[wq*65 + d] = g_q[base + i];
        kr[wq*65 + d] = g_k[base + i];
    }
    __syncthreads();
    const int tx = tid & 15, ty = tid >> 4;
    const int w0 = ty*6, u0 = tx*6;
    float acc[6][6];
    #pragma unroll
    for (int i = 0; i < 6; i++)
        #pragma unroll
        for (int j = 0; j < 6; j++) acc[i][j] = 0.f;
    for (int d = 0; d < 64; d++) {
        float qa[6], ka[6];
        #pragma unroll
        for (int i = 0; i < 6; i++) qa[i] = qr[(w0+i)*65 + d];
        #pragma unroll
        for (int j = 0; j < 6; j++) ka[j] = kr[(u0+j)*65 + d];
        #pragma unroll
        for (int i = 0; i < 6; i++)
            #pragma unroll
            for (int j = 0; j < 6; j++) acc[i][j] = fmaf(qa[i], ka[j], acc[i][j]);
    }
    #pragma unroll
    for (int i = 0; i < 6; i++) {
        size_t sbase = ((size_t)((b*HH + h)*WW) + (w0+i))*LL + 96;
        #pragma unroll
        for (int j = 0; j < 6; j++) g_S[sbase + u0 + j] = acc[i][j];
    }
}

// ---------------------------------------------------------------------------
// K4: softmax over 192, in place. One warp per position.
// ---------------------------------------------------------------------------
__global__ __launch_bounds__(128) void softmax_kernel() {
    const int lane = threadIdx.x & 31;
    const size_t pos = (size_t)blockIdx.x * 4 + (threadIdx.x >> 5);
    float* s = g_S + pos * LL;
    float v[6];
    float m = -3.4e38f;
    #pragma unroll
    for (int i = 0; i < 6; i++) { v[i] = s[lane + 32*i]; m = fmaxf(m, v[i]); }
    #pragma unroll
    for (int o = 16; o; o >>= 1) m = fmaxf(m, __shfl_xor_sync(0xffffffffu, m, o));
    float sum = 0.f;
    #pragma unroll
    for (int i = 0; i < 6; i++) { v[i] = expf(v[i] - m); sum += v[i]; }
    #pragma unroll
    for (int o = 16; o; o >>= 1) sum += __shfl_xor_sync(0xffffffffu, sum, o);
    const float inv = 1.f / sum;
    #pragma unroll
    for (int i = 0; i < 6; i++) s[lane + 32*i] = v[i] * inv;
}

// ---------------------------------------------------------------------------
// K5: yv. One block per (b,w).
// ---------------------------------------------------------------------------
#define SMEM_Y ((96*97 + 96*128)*4)
__global__ __launch_bounds__(256) void yv_kernel() {
    extern __shared__ float sm[];
    float* Av = sm;
    float* Vc = sm + 96*97;
    const int b = blockIdx.y, w = blockIdx.x;
    const int tid = threadIdx.x;
    for (int i = tid; i < 96*96; i += 256) {
        int h = i / 96, g = i - h*96;
        Av[h*97 + g] = g_S[((size_t)((b*HH + h)*WW) + w)*LL + g];
    }
    const int tx = tid & 15, ty = tid >> 4;
    const int h0 = ty*6, ct = tx*8;
    for (int c0 = 0; c0 < CCH; c0 += 128) {
        __syncthreads();
        for (int i = tid*4; i < 96*128; i += 1024) {
            int g = i >> 7, cc = i & 127;
            *reinterpret_cast<float4*>(&Vc[g*128 + cc]) =
                *reinterpret_cast<const float4*>(&g_v[((size_t)((b*HH + g)*WW) + w)*CCH + c0 + cc]);
        }
        __syncthreads();
        float acc[6][8];
        #pragma unroll
        for (int i = 0; i < 6; i++)
            #pragma unroll
            for (int j = 0; j < 8; j++) acc[i][j] = 0.f;
        for (int g = 0; g < 96; g++) {
            float a[6];
            #pragma unroll
            for (int i = 0; i < 6; i++) a[i] = Av[(h0+i)*97 + g];
            float4 v0 = *reinterpret_cast<float4*>(&Vc[g*128 + ct]);
            float4 v1 = *reinterpret_cast<float4*>(&Vc[g*128 + ct + 4]);
            #pragma unroll
            for (int i = 0; i < 6; i++) {
                acc[i][0] = fmaf(a[i], v0.x, acc[i][0]);
                acc[i][1] = fmaf(a[i], v0.y, acc[i][1]);
                acc[i][2] = fmaf(a[i], v0.z, acc[i][2]);
                acc[i][3] = fmaf(a[i], v0.w, acc[i][3]);
                acc[i][4] = fmaf(a[i], v1.x, acc[i][4]);
                acc[i][5] = fmaf(a[i], v1.y, acc[i][5]);
                acc[i][6] = fmaf(a[i], v1.z, acc[i][6]);
                acc[i][7] = fmaf(a[i], v1.w, acc[i][7]);
            }
        }
        #pragma unroll
        for (int i = 0; i < 6; i++) {
            size_t o = ((size_t)((b*HH + h0 + i)*WW) + w)*CCH + c0 + ct;
            *reinterpret_cast<float4*>(&g_yv[o]) =
                make_float4(acc[i][0], acc[i][1], acc[i][2], acc[i][3]);
            *reinterpret_cast<float4*>(&g_yv[o+4]) =
                make_float4(acc[i][4], acc[i][5], acc[i][6], acc[i][7]);
        }
    }
}

// ---------------------------------------------------------------------------
// K6: yh + epilogue. One block per (b,h).
// ---------------------------------------------------------------------------
__global__ __launch_bounds__(256) void yh_final_kernel(
    const float* __restrict__ x, const float* __restrict__ gamma,
    float* __restrict__ out)
{
    extern __shared__ float sm[];
    float* Ah = sm;
    float* Vr = sm + 96*97;
    const int b = blockIdx.y, h = blockIdx.x;
    const int tid = threadIdx.x;
    for (int i = tid; i < 96*96; i += 256) {
        int wq = i / 96, u = i - wq*96;
        Ah[wq*97 + u] = g_S[((size_t)((b*HH + h)*WW) + wq)*LL + 96 + u];
    }
    const float gm = *gamma;
    const int tx = tid & 15, ty = tid >> 4;
    const int w0 = ty*6, ct = tx*8;
    const size_t rowbase = (size_t)(b*HH + h)*WW;
    for (int c0 = 0; c0 < CCH; c0 += 128) {
        __syncthreads();
        for (int i = tid*4; i < 96*128; i += 1024) {
            int u = i >> 7, cc = i & 127;
            *reinterpret_cast<float4*>(&Vr[u*128 + cc]) =
                *reinterpret_cast<const float4*>(&g_v[(rowbase + u)*CCH + c0 + cc]);
        }
        __syncthreads();
        float acc[6][8];
        #pragma unroll
        for (int i = 0; i < 6; i++)
            #pragma unroll
            for (int j = 0; j < 8; j++) acc[i][j] = 0.f;
        for (int u = 0; u < 96; u++) {
            float a[6];
            #pragma unroll
            for (int i = 0; i < 6; i++) a[i] = Ah[(w0+i)*97 + u];
            float4 v0 = *reinterpret_cast<float4*>(&Vr[u*128 + ct]);
            float4 v1 = *reinterpret_cast<float4*>(&Vr[u*128 + ct + 4]);
            #pragma unroll
            for (int i = 0; i < 6; i++) {
                acc[i][0] = fmaf(a[i], v0.x, acc[i][0]);
                acc[i][1] = fmaf(a[i], v0.y, acc[i][1]);
                acc[i][2] = fmaf(a[i], v0.z, acc[i][2]);
                acc[i][3] = fmaf(a[i], v0.w, acc[i][3]);
                acc[i][4] = fmaf(a[i], v1.x, acc[i][4]);
                acc[i][5] = fmaf(a[i], v1.y, acc[i][5]);
                acc[i][6] = fmaf(a[i], v1.z, acc[i][6]);
                acc[i][7] = fmaf(a[i], v1.w, acc[i][7]);
            }
        }
        #pragma unroll
        for (int i = 0; i < 6; i++) {
            size_t o = (rowbase + w0 + i)*CCH + c0 + ct;
            float4 yv0 = *reinterpret_cast<const float4*>(&g_yv[o]);
            float4 yv1 = *reinterpret_cast<const float4*>(&g_yv[o+4]);
            float4 x0  = *reinterpret_cast<const float4*>(&x[o]);
            float4 x1  = *reinterpret_cast<const float4*>(&x[o+4]);
            float4 r0, r1;
            r0.x = fmaf(acc[i][0] + yv0.x, gm, x0.x);
            r0.y = fmaf(acc[i][1] + yv0.y, gm, x0.y);
            r0.z = fmaf(acc[i][2] + yv0.z, gm, x0.z);
            r0.w = fmaf(acc[i][3] + yv0.w, gm, x0.w);
            r1.x = fmaf(acc[i][4] + yv1.x, gm, x1.x);
            r1.y = fmaf(acc[i][5] + yv1.y, gm, x1.y);
            r1.z = fmaf(acc[i][6] + yv1.z, gm, x1.z);
            r1.w = fmaf(acc[i][7] + yv1.w, gm, x1.w);
            *reinterpret_cast<float4*>(&out[o])   = r0;
            *reinterpret_cast<float4*>(&out[o+4]) = r1;
        }
    }
}

// ---------------------------------------------------------------------------
extern "C" void kernel_launch(void* const* d_in, const int* in_sizes, int n_in,
                              void* d_out, int out_size)
{
    const float* x     = (const float*)d_in[0];
    const float* Wq    = (const float*)d_in[1];
    const float* bq    = (const float*)d_in[2];
    const float* Wk    = (const float*)d_in[3];
    const float* bk    = (const float*)d_in[4];
    const float* Wv    = (const float*)d_in[5];
    const float* bv    = (const float*)d_in[6];
    const float* gamma = (const float*)d_in[7];
    float* out = (float*)d_out;

    float *qp, *kp, *vp;
    cudaGetSymbolAddress((void**)&qp, g_q);
    cudaGetSymbolAddress((void**)&kp, g_k);
    cudaGetSymbolAddress((void**)&vp, g_v);

    cudaFuncSetAttribute(proj_mma<128>,   cudaFuncAttributeMaxDynamicSharedMemorySize, P_SMEM_V);
    cudaFuncSetAttribute(proj_mma<64>,    cudaFuncAttributeMaxDynamicSharedMemorySize, P_SMEM_QK);
    cudaFuncSetAttribute(sv_kernel,       cudaFuncAttributeMaxDynamicSharedMemorySize, SMEM_SC);
    cudaFuncSetAttribute(sh_kernel,       cudaFuncAttributeMaxDynamicSharedMemorySize, SMEM_SC);
    cudaFuncSetAttribute(yv_kernel,       cudaFuncAttributeMaxDynamicSharedMemorySize, SMEM_Y);
    cudaFuncSetAttribute(yh_final_kernel, cudaFuncAttributeMaxDynamicSharedMemorySize, SMEM_Y);

    // Projections on tf32 mma.sync tensor cores (fp32 accum, rna conversion)
    proj_mma<128><<<dim3(CCH/128, NPOS/128), 256, P_SMEM_V>>>(x, Wv, bv, vp, CCH);
    proj_mma<64> <<<dim3(1,       NPOS/128), 256, P_SMEM_QK>>>(x, Wq, bq, qp, DD);
    proj_mma<64> <<<dim3(1,       NPOS/128), 256, P_SMEM_QK>>>(x, Wk, bk, kp, DD);

    // Scores (column + row), masked diag in sv
    sv_kernel<<<dim3(WW, BB), 256, SMEM_SC>>>();
    sh_kernel<<<dim3(HH, BB), 256, SMEM_SC>>>();

    // Joint softmax over 192, in place
    softmax_kernel<<<NPOS/4, 128>>>();

    // Attention application + epilogue
    yv_kernel<<<dim3(WW, BB), 256, SMEM_Y>>>();
    yh_final_kernel<<<dim3(HH, BB), 256, SMEM_Y>>>(x, gamma, out);
}

// round 5
// speedup vs baseline: 2.5647x; 1.4337x over previous
#include <cuda_runtime.h>
#include <math.h>
#include <stdint.h>

// Problem dims
#define BB   8
#define HH   96
#define WW   96
#define CCH  512
#define DD   64
#define LL   192
#define NPOS (BB*HH*WW)   // 73728

// ---------------------------------------------------------------------------
// Scratch (device globals; no allocations allowed)
// ---------------------------------------------------------------------------
__device__ float g_q [(size_t)NPOS*DD];
__device__ float g_k [(size_t)NPOS*DD];
__device__ float g_v [(size_t)NPOS*CCH];   // tf32-rounded by proj epilogue
__device__ float g_S [(size_t)NPOS*LL];    // probs tf32-rounded by softmax
__device__ float g_yv[(size_t)NPOS*CCH];
__device__ float g_xt[(size_t)NPOS*CCH];   // tf32-rounded x
__device__ float g_wvt[(size_t)CCH*CCH];   // tf32-rounded weights
__device__ float g_wqt[(size_t)CCH*DD];
__device__ float g_wkt[(size_t)CCH*DD];

// ---------------------------------------------------------------------------
// Helpers (baseline PTX, sm_80+)
// ---------------------------------------------------------------------------
__device__ __forceinline__ uint32_t smem_u32(const void* p) {
    uint32_t a;
    asm("{ .reg .u64 t; cvta.to.shared.u64 t, %1; cvt.u32.u64 %0, t; }" : "=r"(a) : "l"(p));
    return a;
}
__device__ __forceinline__ uint32_t f2tf32(float f) {
    uint32_t r;
    asm("cvt.rna.tf32.f32 %0, %1;" : "=r"(r) : "f"(f));
    return r;
}
__device__ __forceinline__ void mma_tf32(
    float& c0, float& c1, float& c2, float& c3,
    uint32_t a0, uint32_t a1, uint32_t a2, uint32_t a3,
    uint32_t b0, uint32_t b1)
{
    asm volatile(
        "mma.sync.aligned.m16n8k8.row.col.f32.tf32.tf32.f32 "
        "{%0,%1,%2,%3}, {%4,%5,%6,%7}, {%8,%9}, {%0,%1,%2,%3};"
        : "+f"(c0), "+f"(c1), "+f"(c2), "+f"(c3)
        : "r"(a0), "r"(a1), "r"(a2), "r"(a3), "r"(b0), "r"(b1));
}
__device__ __forceinline__ void cpasync16(uint32_t dst, const void* src) {
    asm volatile("cp.async.cg.shared.global [%0], [%1], 16;" :: "r"(dst), "l"(src));
}
#define CP_COMMIT() asm volatile("cp.async.commit_group;" ::: "memory")
#define CP_WAIT(n)  asm volatile("cp.async.wait_group %0;" :: "n"(n) : "memory")

// ---------------------------------------------------------------------------
// P0: tf32 pre-round (vectorized)
// ---------------------------------------------------------------------------
__global__ __launch_bounds__(256) void round_tf32_kernel(
    const float* __restrict__ src, float* __restrict__ dst, size_t n4)
{
    size_t i = (size_t)blockIdx.x * 256 + threadIdx.x;
    if (i >= n4) return;
    float4 v = *reinterpret_cast<const float4*>(src + i * 4);
    float4 o;
    o.x = __uint_as_float(f2tf32(v.x));
    o.y = __uint_as_float(f2tf32(v.y));
    o.z = __uint_as_float(f2tf32(v.z));
    o.w = __uint_as_float(f2tf32(v.w));
    *reinterpret_cast<float4*>(dst + i * 4) = o;
}

// ---------------------------------------------------------------------------
// K1: tf32 projection GEMM (pre-rounded operands; no CVT in inner loop)
//   BM=128, BK=32, BN template. 256 thr = 8 warps (2m x 4n).
//   RND: round outputs to tf32 (for v, which feeds later mma).
// ---------------------------------------------------------------------------
template<int BN, bool RND>
__global__ __launch_bounds__(256) void proj_mma(
    const float* __restrict__ X, const float* __restrict__ W,
    const float* __restrict__ bias, float* __restrict__ C, int M)
{
    constexpr int BM = 128, BK = 32;
    constexpr int AP = 36, BP = BN + 8;
    constexpr int ASZ = BM * AP;
    constexpr int BSZ = BK * BP;
    constexpr int NCH = CCH / BK;
    constexpr int WN  = BN / 4;
    constexpr int NT  = WN / 8;

    extern __shared__ float sm[];
    const uint32_t sbase = smem_u32(sm);
    const int tid = threadIdx.x;
    const int wid = tid >> 5, lane = tid & 31;
    const int gid = lane >> 2, tg = lane & 3;
    const int wm = wid >> 2, wn = wid & 3;
    const int rowBase = blockIdx.y * BM;
    const int n0 = blockIdx.x * BN;

    float acc[4][NT][4];
    #pragma unroll
    for (int mt = 0; mt < 4; mt++)
        #pragma unroll
        for (int nt = 0; nt < NT; nt++)
            #pragma unroll
            for (int i = 0; i < 4; i++) acc[mt][nt][i] = 0.f;

    auto issue = [&](int ch, int buf) {
        const int kc = ch * BK;
        const uint32_t abase = sbase + (uint32_t)(buf * (ASZ + BSZ)) * 4u;
        const uint32_t bbase = abase + (uint32_t)ASZ * 4u;
        #pragma unroll
        for (int i = 0; i < 4; i++) {
            int idx = tid + i * 256;
            int r = idx >> 3, c4 = idx & 7;
            cpasync16(abase + (uint32_t)(r * AP + c4 * 4) * 4u,
                      &X[(size_t)(rowBase + r) * CCH + kc + c4 * 4]);
        }
        #pragma unroll
        for (int i = 0; i < BK * BN / 4 / 256; i++) {
            int idx = tid + i * 256;
            int kr = idx / (BN / 4), c4 = idx % (BN / 4);
            cpasync16(bbase + (uint32_t)(kr * BP + c4 * 4) * 4u,
                      &W[(size_t)(kc + kr) * M + n0 + c4 * 4]);
        }
        CP_COMMIT();
    };

    issue(0, 0);
    for (int ch = 0; ch < NCH; ch++) {
        const int buf = ch & 1;
        if (ch + 1 < NCH) { issue(ch + 1, buf ^ 1); CP_WAIT(1); }
        else              { CP_WAIT(0); }
        __syncthreads();

        const float* Ab = sm + buf * (ASZ + BSZ);
        const float* Bb = Ab + ASZ;
        #pragma unroll
        for (int ks = 0; ks < 4; ks++) {
            const int k0 = ks * 8;
            uint32_t a[4][4];
            #pragma unroll
            for (int mt = 0; mt < 4; mt++) {
                const int m = wm * 64 + mt * 16;
                a[mt][0] = __float_as_uint(Ab[(m + gid)     * AP + k0 + tg]);
                a[mt][1] = __float_as_uint(Ab[(m + 8 + gid) * AP + k0 + tg]);
                a[mt][2] = __float_as_uint(Ab[(m + gid)     * AP + k0 + tg + 4]);
                a[mt][3] = __float_as_uint(Ab[(m + 8 + gid) * AP + k0 + tg + 4]);
            }
            uint32_t b[NT][2];
            #pragma unroll
            for (int nt = 0; nt < NT; nt++) {
                const int col = wn * WN + nt * 8 + gid;
                b[nt][0] = __float_as_uint(Bb[(k0 + tg)     * BP + col]);
                b[nt][1] = __float_as_uint(Bb[(k0 + tg + 4) * BP + col]);
            }
            #pragma unroll
            for (int mt = 0; mt < 4; mt++)
                #pragma unroll
                for (int nt = 0; nt < NT; nt++)
                    mma_tf32(acc[mt][nt][0], acc[mt][nt][1], acc[mt][nt][2], acc[mt][nt][3],
                             a[mt][0], a[mt][1], a[mt][2], a[mt][3],
                             b[nt][0], b[nt][1]);
        }
        __syncthreads();
    }

    #pragma unroll
    for (int mt = 0; mt < 4; mt++) {
        const int row = rowBase + wm * 64 + mt * 16 + gid;
        #pragma unroll
        for (int nt = 0; nt < NT; nt++) {
            const int col = n0 + wn * WN + nt * 8 + tg * 2;
            const float b0 = bias[col], b1 = bias[col + 1];
            float v00 = acc[mt][nt][0] + b0, v01 = acc[mt][nt][1] + b1;
            float v10 = acc[mt][nt][2] + b0, v11 = acc[mt][nt][3] + b1;
            if (RND) {
                v00 = __uint_as_float(f2tf32(v00)); v01 = __uint_as_float(f2tf32(v01));
                v10 = __uint_as_float(f2tf32(v10)); v11 = __uint_as_float(f2tf32(v11));
            }
            C[(size_t)row * M + col]           = v00;
            C[(size_t)row * M + col + 1]       = v01;
            C[(size_t)(row + 8) * M + col]     = v10;
            C[(size_t)(row + 8) * M + col + 1] = v11;
        }
    }
}

#define P_SMEM_V  ((128*36 + 32*(128+8)) * 2 * 4)
#define P_SMEM_QK ((128*36 + 32*(64+8)) * 2 * 4)

// ---------------------------------------------------------------------------
// K2: sv scores (fp32; diag masked)
// ---------------------------------------------------------------------------
#define SMEM_SC (2*96*65*4)
__global__ __launch_bounds__(256) void sv_kernel() {
    extern __shared__ float sm[];
    float* qc = sm;
    float* kc = sm + 96*65;
    const int b = blockIdx.y, w = blockIdx.x;
    const int tid = threadIdx.x;
    for (int i = tid; i < 96*64; i += 256) {
        int h = i >> 6, d = i & 63;
        size_t gi = ((size_t)((b*HH + h)*WW) + w)*DD + d;
        qc[h*65 + d] = g_q[gi];
        kc[h*65 + d] = g_k[gi];
    }
    __syncthreads();
    const int tx = tid & 15, ty = tid >> 4;
    const int h0 = ty*6, g0 = tx*6;
    float acc[6][6];
    #pragma unroll
    for (int i = 0; i < 6; i++)
        #pragma unroll
        for (int j = 0; j < 6; j++) acc[i][j] = 0.f;
    for (int d = 0; d < 64; d++) {
        float qa[6], ka[6];
        #pragma unroll
        for (int i = 0; i < 6; i++) qa[i] = qc[(h0+i)*65 + d];
        #pragma unroll
        for (int j = 0; j < 6; j++) ka[j] = kc[(g0+j)*65 + d];
        #pragma unroll
        for (int i = 0; i < 6; i++)
            #pragma unroll
            for (int j = 0; j < 6; j++) acc[i][j] = fmaf(qa[i], ka[j], acc[i][j]);
    }
    #pragma unroll
    for (int i = 0; i < 6; i++) {
        int h = h0 + i;
        size_t base = ((size_t)((b*HH + h)*WW) + w)*LL;
        #pragma unroll
        for (int j = 0; j < 6; j++) {
            int g = g0 + j;
            g_S[base + g] = (g == h) ? -1e30f : acc[i][j];
        }
    }
}

// ---------------------------------------------------------------------------
// K3: sh scores (fp32)
// ---------------------------------------------------------------------------
__global__ __launch_bounds__(256) void sh_kernel() {
    extern __shared__ float sm[];
    float* qr = sm;
    float* kr = sm + 96*65;
    const int b = blockIdx.y, h = blockIdx.x;
    const int tid = threadIdx.x;
    const size_t base = (size_t)(b*HH + h)*WW*DD;
    for (int i = tid; i < 96*64; i += 256) {
        int wq = i >> 6, d = i & 63;
        qr[wq*65 + d] = g_q[base + i];
        kr[wq*65 + d] = g_k[base + i];
    }
    __syncthreads();
    const int tx = tid & 15, ty = tid >> 4;
    const int w0 = ty*6, u0 = tx*6;
    float acc[6][6];
    #pragma unroll
    for (int i = 0; i < 6; i++)
        #pragma unroll
        for (int j = 0; j < 6; j++) acc[i][j] = 0.f;
    for (int d = 0; d < 64; d++) {
        float qa[6], ka[6];
        #pragma unroll
        for (int i = 0; i < 6; i++) qa[i] = qr[(w0+i)*65 + d];
        #pragma unroll
        for (int j = 0; j < 6; j++) ka[j] = kr[(u0+j)*65 + d];
        #pragma unroll
        for (int i = 0; i < 6; i++)
            #pragma unroll
            for (int j = 0; j < 6; j++) acc[i][j] = fmaf(qa[i], ka[j], acc[i][j]);
    }
    #pragma unroll
    for (int i = 0; i < 6; i++) {
        size_t sbase = ((size_t)((b*HH + h)*WW) + (w0+i))*LL + 96;
        #pragma unroll
        for (int j = 0; j < 6; j++) g_S[sbase + u0 + j] = acc[i][j];
    }
}

// ---------------------------------------------------------------------------
// K4: softmax over 192, in place; writes tf32-rounded probs.
// ---------------------------------------------------------------------------
__global__ __launch_bounds__(128) void softmax_kernel() {
    const int lane = threadIdx.x & 31;
    const size_t pos = (size_t)blockIdx.x * 4 + (threadIdx.x >> 5);
    float* s = g_S + pos * LL;
    float v[6];
    float m = -3.4e38f;
    #pragma unroll
    for (int i = 0; i < 6; i++) { v[i] = s[lane + 32*i]; m = fmaxf(m, v[i]); }
    #pragma unroll
    for (int o = 16; o; o >>= 1) m = fmaxf(m, __shfl_xor_sync(0xffffffffu, m, o));
    float sum = 0.f;
    #pragma unroll
    for (int i = 0; i < 6; i++) { v[i] = expf(v[i] - m); sum += v[i]; }
    #pragma unroll
    for (int o = 16; o; o >>= 1) sum += __shfl_xor_sync(0xffffffffu, sum, o);
    const float inv = 1.f / sum;
    #pragma unroll
    for (int i = 0; i < 6; i++)
        s[lane + 32*i] = __uint_as_float(f2tf32(v[i] * inv));
}

// ---------------------------------------------------------------------------
// K5/K6: attention apply on tf32 mma.
//   yv:  block (cchunk, w, b): Y[h, c] = sum_g A[h,g] V[b,g,w,c]
//   yh:  block (cchunk, h, b): out[w,c] = (sum_u A[w,u] V[b,h,u,c] + yv)*gm + x
//   M=96 (2 warp-m x 48 = 3 m16), N=128 (4 warp-n x 32 = 4 n8), K=96 (12 k8)
// ---------------------------------------------------------------------------
#define AT_AP 100
#define AT_BP 136
#define AT_SMEM ((96*AT_AP + 96*AT_BP)*4)   // 90624 B

__global__ __launch_bounds__(256) void yv_mma() {
    extern __shared__ float sm[];
    float* As = sm;
    float* Bs = sm + 96*AT_AP;
    const uint32_t sbase = smem_u32(sm);
    const int b = blockIdx.z, w = blockIdx.y, c0 = blockIdx.x * 128;
    const int tid = threadIdx.x;
    const int wid = tid >> 5, lane = tid & 31;
    const int gid = lane >> 2, tg = lane & 3;
    const int wm = wid >> 2, wn = wid & 3;

    // A: probs[h=0..95][g=0..95] (96 rows x 24 float4)
    for (int i = tid; i < 96*24; i += 256) {
        int h = i / 24, c4 = i % 24;
        cpasync16(sbase + (uint32_t)(h*AT_AP + c4*4)*4u,
                  &g_S[((size_t)((b*HH + h)*WW) + w)*LL + c4*4]);
    }
    // B: V[g=0..95][c0..c0+127] (96 rows x 32 float4)
    for (int i = tid; i < 96*32; i += 256) {
        int g = i >> 5, c4 = i & 31;
        cpasync16(sbase + (uint32_t)(96*AT_AP + g*AT_BP + c4*4)*4u,
                  &g_v[((size_t)((b*HH + g)*WW) + w)*CCH + c0 + c4*4]);
    }
    CP_COMMIT(); CP_WAIT(0);
    __syncthreads();

    float acc[3][4][4];
    #pragma unroll
    for (int mt = 0; mt < 3; mt++)
        #pragma unroll
        for (int nt = 0; nt < 4; nt++)
            #pragma unroll
            for (int i = 0; i < 4; i++) acc[mt][nt][i] = 0.f;

    #pragma unroll
    for (int ks = 0; ks < 12; ks++) {
        const int k0 = ks * 8;
        uint32_t a[3][4];
        #pragma unroll
        for (int mt = 0; mt < 3; mt++) {
            const int m = wm * 48 + mt * 16;
            a[mt][0] = __float_as_uint(As[(m + gid)     * AT_AP + k0 + tg]);
            a[mt][1] = __float_as_uint(As[(m + 8 + gid) * AT_AP + k0 + tg]);
            a[mt][2] = __float_as_uint(As[(m + gid)     * AT_AP + k0 + tg + 4]);
            a[mt][3] = __float_as_uint(As[(m + 8 + gid) * AT_AP + k0 + tg + 4]);
        }
        uint32_t bf[4][2];
        #pragma unroll
        for (int nt = 0; nt < 4; nt++) {
            const int col = wn * 32 + nt * 8 + gid;
            bf[nt][0] = __float_as_uint(Bs[(k0 + tg)     * AT_BP + col]);
            bf[nt][1] = __float_as_uint(Bs[(k0 + tg + 4) * AT_BP + col]);
        }
        #pragma unroll
        for (int mt = 0; mt < 3; mt++)
            #pragma unroll
            for (int nt = 0; nt < 4; nt++)
                mma_tf32(acc[mt][nt][0], acc[mt][nt][1], acc[mt][nt][2], acc[mt][nt][3],
                         a[mt][0], a[mt][1], a[mt][2], a[mt][3],
                         bf[nt][0], bf[nt][1]);
    }

    #pragma unroll
    for (int mt = 0; mt < 3; mt++) {
        const int row0 = wm * 48 + mt * 16 + gid;
        #pragma unroll
        for (int nt = 0; nt < 4; nt++) {
            const int col = c0 + wn * 32 + nt * 8 + tg * 2;
            size_t o0 = ((size_t)((b*HH + row0)*WW) + w)*CCH + col;
            size_t o1 = ((size_t)((b*HH + row0 + 8)*WW) + w)*CCH + col;
            *reinterpret_cast<float2*>(&g_yv[o0]) = make_float2(acc[mt][nt][0], acc[mt][nt][1]);
            *reinterpret_cast<float2*>(&g_yv[o1]) = make_float2(acc[mt][nt][2], acc[mt][nt][3]);
        }
    }
}

__global__ __launch_bounds__(256) void yh_mma(
    const float* __restrict__ x, const float* __restrict__ gamma,
    float* __restrict__ out)
{
    extern __shared__ float sm[];
    float* As = sm;
    float* Bs = sm + 96*AT_AP;
    const uint32_t sbase = smem_u32(sm);
    const int b = blockIdx.z, h = blockIdx.y, c0 = blockIdx.x * 128;
    const int tid = threadIdx.x;
    const int wid = tid >> 5, lane = tid & 31;
    const int gid = lane >> 2, tg = lane & 3;
    const int wm = wid >> 2, wn = wid & 3;
    const size_t rowbase = (size_t)(b*HH + h)*WW;

    // A: probs[w=0..95][u=0..95] from S[..., 96+u]
    for (int i = tid; i < 96*24; i += 256) {
        int r = i / 24, c4 = i % 24;
        cpasync16(sbase + (uint32_t)(r*AT_AP + c4*4)*4u,
                  &g_S[(rowbase + r)*LL + 96 + c4*4]);
    }
    // B: V[u=0..95][c0..c0+127] (contiguous rows within the line)
    for (int i = tid; i < 96*32; i += 256) {
        int u = i >> 5, c4 = i & 31;
        cpasync16(sbase + (uint32_t)(96*AT_AP + u*AT_BP + c4*4)*4u,
                  &g_v[(rowbase + u)*CCH + c0 + c4*4]);
    }
    CP_COMMIT(); CP_WAIT(0);
    __syncthreads();

    float acc[3][4][4];
    #pragma unroll
    for (int mt = 0; mt < 3; mt++)
        #pragma unroll
        for (int nt = 0; nt < 4; nt++)
            #pragma unroll
            for (int i = 0; i < 4; i++) acc[mt][nt][i] = 0.f;

    #pragma unroll
    for (int ks = 0; ks < 12; ks++) {
        const int k0 = ks * 8;
        uint32_t a[3][4];
        #pragma unroll
        for (int mt = 0; mt < 3; mt++) {
            const int m = wm * 48 + mt * 16;
            a[mt][0] = __float_as_uint(As[(m + gid)     * AT_AP + k0 + tg]);
            a[mt][1] = __float_as_uint(As[(m + 8 + gid) * AT_AP + k0 + tg]);
            a[mt][2] = __float_as_uint(As[(m + gid)     * AT_AP + k0 + tg + 4]);
            a[mt][3] = __float_as_uint(As[(m + 8 + gid) * AT_AP + k0 + tg + 4]);
        }
        uint32_t bf[4][2];
        #pragma unroll
        for (int nt = 0; nt < 4; nt++) {
            const int col = wn * 32 + nt * 8 + gid;
            bf[nt][0] = __float_as_uint(Bs[(k0 + tg)     * AT_BP + col]);
            bf[nt][1] = __float_as_uint(Bs[(k0 + tg + 4) * AT_BP + col]);
        }
        #pragma unroll
        for (int mt = 0; mt < 3; mt++)
            #pragma unroll
            for (int nt = 0; nt < 4; nt++)
                mma_tf32(acc[mt][nt][0], acc[mt][nt][1], acc[mt][nt][2], acc[mt][nt][3],
                         a[mt][0], a[mt][1], a[mt][2], a[mt][3],
                         bf[nt][0], bf[nt][1]);
    }

    const float gm = *gamma;
    #pragma unroll
    for (int mt = 0; mt < 3; mt++) {
        const int row0 = wm * 48 + mt * 16 + gid;
        #pragma unroll
        for (int nt = 0; nt < 4; nt++) {
            const int col = c0 + wn * 32 + nt * 8 + tg * 2;
            size_t o0 = (rowbase + row0)*CCH + col;
            size_t o1 = (rowbase + row0 + 8)*CCH + col;
            float2 yv0 = *reinterpret_cast<const float2*>(&g_yv[o0]);
            float2 yv1 = *reinterpret_cast<const float2*>(&g_yv[o1]);
            float2 x0  = *reinterpret_cast<const float2*>(&x[o0]);
            float2 x1  = *reinterpret_cast<const float2*>(&x[o1]);
            float2 r0, r1;
            r0.x = fmaf(acc[mt][nt][0] + yv0.x, gm, x0.x);
            r0.y = fmaf(acc[mt][nt][1] + yv0.y, gm, x0.y);
            r1.x = fmaf(acc[mt][nt][2] + yv1.x, gm, x1.x);
            r1.y = fmaf(acc[mt][nt][3] + yv1.y, gm, x1.y);
            *reinterpret_cast<float2*>(&out[o0]) = r0;
            *reinterpret_cast<float2*>(&out[o1]) = r1;
        }
    }
}

// ---------------------------------------------------------------------------
extern "C" void kernel_launch(void* const* d_in, const int* in_sizes, int n_in,
                              void* d_out, int out_size)
{
    const float* x     = (const float*)d_in[0];
    const float* Wq    = (const float*)d_in[1];
    const float* bq    = (const float*)d_in[2];
    const float* Wk    = (const float*)d_in[3];
    const float* bk    = (const float*)d_in[4];
    const float* Wv    = (const float*)d_in[5];
    const float* bv    = (const float*)d_in[6];
    const float* gamma = (const float*)d_in[7];
    float* out = (float*)d_out;

    float *qp, *kp, *vp, *xt, *wvt, *wqt, *wkt;
    cudaGetSymbolAddress((void**)&qp,  g_q);
    cudaGetSymbolAddress((void**)&kp,  g_k);
    cudaGetSymbolAddress((void**)&vp,  g_v);
    cudaGetSymbolAddress((void**)&xt,  g_xt);
    cudaGetSymbolAddress((void**)&wvt, g_wvt);
    cudaGetSymbolAddress((void**)&wqt, g_wqt);
    cudaGetSymbolAddress((void**)&wkt, g_wkt);

    cudaFuncSetAttribute(proj_mma<128,true>, cudaFuncAttributeMaxDynamicSharedMemorySize, P_SMEM_V);
    cudaFuncSetAttribute(proj_mma<64,false>, cudaFuncAttributeMaxDynamicSharedMemorySize, P_SMEM_QK);
    cudaFuncSetAttribute(sv_kernel, cudaFuncAttributeMaxDynamicSharedMemorySize, SMEM_SC);
    cudaFuncSetAttribute(sh_kernel, cudaFuncAttributeMaxDynamicSharedMemorySize, SMEM_SC);
    cudaFuncSetAttribute(yv_mma,    cudaFuncAttributeMaxDynamicSharedMemorySize, AT_SMEM);
    cudaFuncSetAttribute(yh_mma,    cudaFuncAttributeMaxDynamicSharedMemorySize, AT_SMEM);

    // tf32 pre-round x and weights
    round_tf32_kernel<<<(NPOS*CCH/4 + 255)/256, 256>>>(x,  xt,  (size_t)NPOS*CCH/4);
    round_tf32_kernel<<<(CCH*CCH/4  + 255)/256, 256>>>(Wv, wvt, (size_t)CCH*CCH/4);
    round_tf32_kernel<<<(CCH*DD/4   + 255)/256, 256>>>(Wq, wqt, (size_t)CCH*DD/4);
    round_tf32_kernel<<<(CCH*DD/4   + 255)/256, 256>>>(Wk, wkt, (size_t)CCH*DD/4);

    // Projections (v output rounded to tf32 for the downstream mma)
    proj_mma<128,true> <<<dim3(CCH/128, NPOS/128), 256, P_SMEM_V>>>(xt, wvt, bv, vp, CCH);
    proj_mma<64,false> <<<dim3(1,       NPOS/128), 256, P_SMEM_QK>>>(xt, wqt, bq, qp, DD);
    proj_mma<64,false> <<<dim3(1,       NPOS/128), 256, P_SMEM_QK>>>(xt, wkt, bk, kp, DD);

    // Scores + joint softmax (probs rounded to tf32)
    sv_kernel<<<dim3(WW, BB), 256, SMEM_SC>>>();
    sh_kernel<<<dim3(HH, BB), 256, SMEM_SC>>>();
    softmax_kernel<<<NPOS/4, 128>>>();

    // Attention apply on tensor cores
    yv_mma<<<dim3(4, WW, BB), 256, AT_SMEM>>>();
    yh_mma<<<dim3(4, HH, BB), 256, AT_SMEM>>>(x, gamma, out);
}